// round 1
// baseline (speedup 1.0000x reference)
#include <cuda_runtime.h>
#include <math.h>

#define T_STEPS 64
#define BATCH   256

// ---------------- scratch (static device allocations) ----------------
__device__ float g_Aproj[T_STEPS * BATCH * 1024];  // actions @ Wi1_act + bi1
__device__ float g_Oproj[T_STEPS * BATCH * 1024];  // obs @ Wo1_top + bo1
__device__ float g_Wbig[2048 * 3072];              // [Wi2@Wg_top ; Wg_bot]
__device__ float g_bfold[3072];                    // bi2 @ Wg_top
__device__ float g_Wcat[1024 * 2048];              // [Wp1 | Wo1_bot]
__device__ float g_hb[BATCH * 2048];               // [h1 | b]
__device__ float g_G[BATCH * 3072];                // gru gates pre-LN
__device__ float g_hq[BATCH * 2048];               // [h_prior | h_post]
__device__ float g_lg[BATCH * 2048];               // [prior_logits | post_logits]
__device__ int   g_zidx[BATCH * 32];               // sampled one-hot indices

__device__ __forceinline__ float siluf(float x) { return x / (1.0f + expf(-x)); }
__device__ __forceinline__ float sigm(float x)  { return 1.0f / (1.0f + expf(-x)); }

// ---------------- generic 64x64 tiled fp32 GEMM ----------------
// C[M,N] = A[M,K] @ W[K,N] with epilogue MODE:
//  0: + bias[n] (bias may be null)
//  1: silu(acc + aux[m*auxld + n])                          (step0 h1)
//  2: logits split: n<1024 uses (A,W,bias); n>=1024 uses (A+1024,W2,bias2)
//  3: n<1024: silu(acc+bias[n]); n>=1024: silu(acc+aux[m*1024+(n-1024)])
#define BM 64
#define BN 64
#define BKT 16

template <int MODE>
__global__ void gemm_k(const float* __restrict__ A, int lda,
                       const float* __restrict__ W, int ldw,
                       float* __restrict__ C, int ldc,
                       int K,
                       const float* __restrict__ bias,
                       const float* __restrict__ aux, int auxld,
                       const float* __restrict__ W2,
                       const float* __restrict__ bias2) {
    __shared__ float As[BKT][BM + 4];
    __shared__ float Bs[BKT][BN];

    const int bn = blockIdx.x * BN;
    const int bm = blockIdx.y * BM;
    const int tid = threadIdx.x;

    int wn = bn;  // column base in W/bias space
    if (MODE == 2) {
        if (bn >= 1024) { A += 1024; W = W2; bias = bias2; wn = bn - 1024; }
    }

    const int tx = tid & 15, ty = tid >> 4;
    const int arow = tid >> 2, avec = tid & 3;   // A tile: 64 rows x 4 float4
    const int wrow = tid >> 4, wvec = tid & 15;  // W tile: 16 rows x 16 float4

    float acc[4][4];
#pragma unroll
    for (int i = 0; i < 4; i++)
#pragma unroll
        for (int j = 0; j < 4; j++) acc[i][j] = 0.0f;

    for (int k0 = 0; k0 < K; k0 += BKT) {
        float4 a4 = *(const float4*)(A + (size_t)(bm + arow) * lda + k0 + avec * 4);
        As[avec * 4 + 0][arow] = a4.x;
        As[avec * 4 + 1][arow] = a4.y;
        As[avec * 4 + 2][arow] = a4.z;
        As[avec * 4 + 3][arow] = a4.w;
        float4 w4 = *(const float4*)(W + (size_t)(k0 + wrow) * ldw + wn + wvec * 4);
        *(float4*)&Bs[wrow][wvec * 4] = w4;
        __syncthreads();
#pragma unroll
        for (int k = 0; k < BKT; k++) {
            float4 ar = *(const float4*)&As[k][ty * 4];
            float4 br = *(const float4*)&Bs[k][tx * 4];
            acc[0][0] += ar.x * br.x; acc[0][1] += ar.x * br.y;
            acc[0][2] += ar.x * br.z; acc[0][3] += ar.x * br.w;
            acc[1][0] += ar.y * br.x; acc[1][1] += ar.y * br.y;
            acc[1][2] += ar.y * br.z; acc[1][3] += ar.y * br.w;
            acc[2][0] += ar.z * br.x; acc[2][1] += ar.z * br.y;
            acc[2][2] += ar.z * br.z; acc[2][3] += ar.z * br.w;
            acc[3][0] += ar.w * br.x; acc[3][1] += ar.w * br.y;
            acc[3][2] += ar.w * br.z; acc[3][3] += ar.w * br.w;
        }
        __syncthreads();
    }

#pragma unroll
    for (int i = 0; i < 4; i++) {
        int m = bm + ty * 4 + i;
#pragma unroll
        for (int j = 0; j < 4; j++) {
            int gn = bn + tx * 4 + j;        // global output column
            int lc = wn + tx * 4 + j;        // local (W/bias-space) column
            float v = acc[i][j];
            if (MODE == 0) {
                if (bias) v += bias[gn];
            } else if (MODE == 1) {
                v = siluf(v + aux[(size_t)m * auxld + gn]);
            } else if (MODE == 2) {
                v += bias[lc];
            } else if (MODE == 3) {
                if (gn < 1024) v = siluf(v + bias[gn]);
                else           v = siluf(v + aux[(size_t)m * 1024 + (gn - 1024)]);
            }
            C[(size_t)m * ldc + gn] = v;
        }
    }
}

// ---------------- small prep kernels ----------------
__global__ void k_aproj(const float* __restrict__ actions, const float* __restrict__ Wi1,
                        const float* __restrict__ bi1, float* __restrict__ out) {
    int idx = blockIdx.x * 256 + threadIdx.x;  // over T*B*1024
    int r = idx >> 10, j = idx & 1023;
    const float* act = actions + (size_t)r * 6;
    float acc = bi1[j];
#pragma unroll
    for (int q = 0; q < 6; q++) acc += act[q] * Wi1[(size_t)(1024 + q) * 1024 + j];
    out[idx] = acc;
}

__global__ void k_bfold(const float* __restrict__ bi2, const float* __restrict__ Wg,
                        float* __restrict__ bf) {
    int n = blockIdx.x * 256 + threadIdx.x;
    if (n >= 3072) return;
    float acc = 0.0f;
    for (int k = 0; k < 1024; k++) acc += bi2[k] * Wg[(size_t)k * 3072 + n];
    bf[n] = acc;
}

__global__ void k_copy_wg_bot(const float* __restrict__ Wg, float* __restrict__ Wbig) {
    size_t idx = (size_t)blockIdx.x * 256 + threadIdx.x;  // over 1024*3072
    Wbig[(size_t)1024 * 3072 + idx] = Wg[(size_t)1024 * 3072 + idx];
}

__global__ void k_wcat(const float* __restrict__ Wp1, const float* __restrict__ Wo1,
                       float* __restrict__ Wcat) {
    int idx = blockIdx.x * 256 + threadIdx.x;  // over 1024*2048
    int k = idx >> 11, n = idx & 2047;
    Wcat[idx] = (n < 1024) ? Wp1[(size_t)k * 1024 + n]
                           : Wo1[(size_t)(1024 + k) * 1024 + (n - 1024)];
}

__global__ void k_inithb(const float* __restrict__ b0, float* __restrict__ hb) {
    int idx = blockIdx.x * 256 + threadIdx.x;  // over 256*1024
    int m = idx >> 10, j = idx & 1023;
    hb[(size_t)m * 2048 + 1024 + j] = b0[idx];
}

// one-hot z gather:  h1 = silu(Aproj[t] + sum_s Wi1[zidx[s]])
__global__ void k_zgather(const float* __restrict__ Wi1, const float* __restrict__ Aproj_t,
                          const int* __restrict__ zidx, float* __restrict__ hb) {
    int row = blockIdx.x, tid = threadIdx.x;
    __shared__ int idxs[32];
    if (tid < 32) idxs[tid] = zidx[row * 32 + tid];
    __syncthreads();
    for (int j = tid; j < 1024; j += 256) {
        float acc = Aproj_t[(size_t)row * 1024 + j];
#pragma unroll
        for (int s = 0; s < 32; s++) acc += Wi1[(size_t)idxs[s] * 1024 + j];
        hb[(size_t)row * 2048 + j] = siluf(acc);
    }
}

// LayerNorm(3072) + GRU cell; b updated in place at hb[:,1024:2048]
__global__ void k_ln_gru(const float* __restrict__ G, const float* __restrict__ ls,
                         const float* __restrict__ lb, float* __restrict__ hb) {
    int row = blockIdx.x, tid = threadIdx.x;
    const float* g = G + (size_t)row * 3072;
    __shared__ float red[256];
    __shared__ float mu_s, inv_s;
    float s = 0.0f;
    for (int j = tid; j < 3072; j += 256) s += g[j];
    red[tid] = s; __syncthreads();
    for (int o = 128; o > 0; o >>= 1) { if (tid < o) red[tid] += red[tid + o]; __syncthreads(); }
    if (tid == 0) mu_s = red[0] * (1.0f / 3072.0f);
    __syncthreads();
    float mu = mu_s;
    s = 0.0f;
    for (int j = tid; j < 3072; j += 256) { float d = g[j] - mu; s += d * d; }
    red[tid] = s; __syncthreads();
    for (int o = 128; o > 0; o >>= 1) { if (tid < o) red[tid] += red[tid + o]; __syncthreads(); }
    if (tid == 0) inv_s = 1.0f / sqrtf(red[0] * (1.0f / 3072.0f) + 1e-3f);
    __syncthreads();
    float inv = inv_s;
    float* b = hb + (size_t)row * 2048 + 1024;
    for (int j = tid; j < 1024; j += 256) {
        float r = (g[j]        - mu) * inv * ls[j]        + lb[j];
        float c = (g[1024 + j] - mu) * inv * ls[1024 + j] + lb[1024 + j];
        float u = (g[2048 + j] - mu) * inv * ls[2048 + j] + lb[2048 + j];
        float reset = sigm(r);
        float cand  = tanhf(reset * c);
        float upd   = sigm(u - 1.0f);
        float bo = b[j];
        b[j] = upd * cand + (1.0f - upd) * bo;
    }
}

__device__ __forceinline__ float wmax(float v) {
#pragma unroll
    for (int o = 16; o > 0; o >>= 1) v = fmaxf(v, __shfl_xor_sync(0xffffffffu, v, o));
    return v;
}
__device__ __forceinline__ float wsum(float v) {
#pragma unroll
    for (int o = 16; o > 0; o >>= 1) v += __shfl_xor_sync(0xffffffffu, v, o);
    return v;
}

// softmax+unimix for prior/post, KL, gumbel-max sample, loss
__global__ void k_head(const float* __restrict__ lg, const float* __restrict__ un,
                       float* __restrict__ out, int* __restrict__ zidx) {
    int row = blockIdx.x, tid = threadIdx.x;
    int lane = tid & 31, w = tid >> 5;
    __shared__ float klp[32];
    const float* base = lg + (size_t)row * 2048;
    for (int sg = w; sg < 32; sg += 8) {
        float pl = base[sg * 32 + lane];
        pl = fminf(fmaxf(pl, -20.0f), 20.0f);
        float mx = wmax(pl);
        float e = expf(pl - mx);
        float sm = wsum(e);
        float pp = e / sm * 0.99f + 0.0003125f;

        float ql = base[1024 + sg * 32 + lane];
        ql = fminf(fmaxf(ql, -20.0f), 20.0f);
        float mx2 = wmax(ql);
        float e2 = expf(ql - mx2);
        float sm2 = wsum(e2);
        float qp = e2 / sm2 * 0.99f + 0.0003125f;

        float kle = qp * (logf(qp + 1e-8f) - logf(pp + 1e-8f));
        float kl = wsum(kle);

        float u = un[(size_t)(row * 32 + sg) * 32 + lane];
        float gg = -logf(-logf(u + 1e-6f) + 1e-6f);
        float val = logf(fmaxf(qp, 1e-6f)) + gg;
        int idx = lane;
#pragma unroll
        for (int o = 16; o > 0; o >>= 1) {
            float ov = __shfl_down_sync(0xffffffffu, val, o);
            int   oi = __shfl_down_sync(0xffffffffu, idx, o);
            if (ov > val || (ov == val && oi < idx)) { val = ov; idx = oi; }
        }
        if (lane == 0) { klp[sg] = kl; zidx[row * 32 + sg] = sg * 32 + idx; }
    }
    __syncthreads();
    if (tid == 0) {
        float kl = 0.0f;
        for (int s = 0; s < 32; s++) kl += klp[s];
        float m = fmaxf(kl, 0.1f);
        out[row] = 1.0f * m + 0.1f * m;   // dyn_scale*dyn + rep_scale*rep (identical kl)
    }
}

// ---------------- launch ----------------
extern "C" void kernel_launch(void* const* d_in, const int* in_sizes, int n_in,
                              void* d_out, int out_size) {
    const float* b0      = (const float*)d_in[0];
    const float* z0      = (const float*)d_in[1];
    const float* actions = (const float*)d_in[2];
    const float* obs     = (const float*)d_in[3];
    const float* u_noise = (const float*)d_in[4];
    const float* Wi1     = (const float*)d_in[5];
    const float* bi1     = (const float*)d_in[6];
    const float* Wi2     = (const float*)d_in[7];
    const float* bi2     = (const float*)d_in[8];
    const float* Wg      = (const float*)d_in[9];
    const float* ln_s    = (const float*)d_in[10];
    const float* ln_b    = (const float*)d_in[11];
    const float* Wo1     = (const float*)d_in[12];
    const float* bo1     = (const float*)d_in[13];
    const float* Wo2     = (const float*)d_in[14];
    const float* bo2     = (const float*)d_in[15];
    const float* Wp1     = (const float*)d_in[16];
    const float* bp1     = (const float*)d_in[17];
    const float* Wp2     = (const float*)d_in[18];
    const float* bp2     = (const float*)d_in[19];
    float* out = (float*)d_out;

    float *Aproj, *Oproj, *Wbig, *bfold, *Wcat, *hb, *G, *hq, *lgp;
    int* zidx;
    cudaGetSymbolAddress((void**)&Aproj, g_Aproj);
    cudaGetSymbolAddress((void**)&Oproj, g_Oproj);
    cudaGetSymbolAddress((void**)&Wbig,  g_Wbig);
    cudaGetSymbolAddress((void**)&bfold, g_bfold);
    cudaGetSymbolAddress((void**)&Wcat,  g_Wcat);
    cudaGetSymbolAddress((void**)&hb,    g_hb);
    cudaGetSymbolAddress((void**)&G,     g_G);
    cudaGetSymbolAddress((void**)&hq,    g_hq);
    cudaGetSymbolAddress((void**)&lgp,   g_lg);
    cudaGetSymbolAddress((void**)&zidx,  g_zidx);

    // ---- per-launch precompute (time-parallel) ----
    k_aproj<<<T_STEPS * BATCH * 1024 / 256, 256>>>(actions, Wi1, bi1, Aproj);
    // Oproj = obs @ Wo1_top + bo1   (16384 x 1024 x 1024)
    gemm_k<0><<<dim3(1024 / BN, T_STEPS * BATCH / BM), 256>>>(
        obs, 1024, Wo1, 1024, Oproj, 1024, 1024, bo1, nullptr, 0, nullptr, nullptr);
    // Wbig_top = Wi2 @ Wg_top   (1024 x 3072 x 1024)
    gemm_k<0><<<dim3(3072 / BN, 1024 / BM), 256>>>(
        Wi2, 1024, Wg, 3072, Wbig, 3072, 1024, nullptr, nullptr, 0, nullptr, nullptr);
    k_copy_wg_bot<<<1024 * 3072 / 256, 256>>>(Wg, Wbig);
    k_bfold<<<12, 256>>>(bi2, Wg, bfold);
    k_wcat<<<1024 * 2048 / 256, 256>>>(Wp1, Wo1, Wcat);
    k_inithb<<<BATCH * 1024 / 256, 256>>>(b0, hb);

    // ---- sequential scan ----
    for (int t = 0; t < T_STEPS; t++) {
        if (t == 0) {
            // dense z0: h1 = silu(z0 @ Wi1_top + Aproj[0])
            gemm_k<1><<<dim3(1024 / BN, BATCH / BM), 256>>>(
                z0, 1024, Wi1, 1024, hb, 2048, 1024,
                nullptr, Aproj, 1024, nullptr, nullptr);
        } else {
            k_zgather<<<BATCH, 256>>>(Wi1, Aproj + (size_t)t * BATCH * 1024, zidx, hb);
        }
        // gates = [h1|b] @ Wbig + bfold   (256 x 3072 x 2048)
        gemm_k<0><<<dim3(3072 / BN, BATCH / BM), 256>>>(
            hb, 2048, Wbig, 3072, G, 3072, 2048, bfold, nullptr, 0, nullptr, nullptr);
        k_ln_gru<<<BATCH, 256>>>(G, ln_s, ln_b, hb);
        // hq = silu(b_new @ [Wp1|Wo1_bot] + {bp1 | Oproj[t]})   (256 x 2048 x 1024)
        gemm_k<3><<<dim3(2048 / BN, BATCH / BM), 256>>>(
            hb + 1024, 2048, Wcat, 2048, hq, 2048, 1024,
            bp1, Oproj + (size_t)t * BATCH * 1024, 1024, nullptr, nullptr);
        // logits: [h_p @ Wp2 + bp2 | h_o @ Wo2 + bo2]
        gemm_k<2><<<dim3(2048 / BN, BATCH / BM), 256>>>(
            hq, 2048, Wp2, 1024, lgp, 2048, 1024,
            bp2, nullptr, 0, Wo2, bo2);
        k_head<<<BATCH, 256>>>(lgp, u_noise + (size_t)t * BATCH * 1024,
                               out + t * BATCH, zidx);
    }
}